// round 5
// baseline (speedup 1.0000x reference)
#include <cuda_runtime.h>
#include <cstdint>

// Problem constants (fixed by the dataset)
#define RWIN   3
#define NW     49          // (2R+1)^2
#define NSIDE  128
#define NN     (NSIDE*NSIDE)
#define KCH    131
#define CCH    21
#define BB     2

// Scratch (device globals; no allocation allowed)
// g_TU[b][k][pix] = (exp(xm), exp(-xm))  where xm = intergrated * mask
__device__ float2 g_TU[(size_t)BB * KCH * NN];
// g_A[w][b][pix] : per-window-tap mixing weights (49 planes, coalesced for gather)
__device__ float  g_A[(size_t)NW * BB * NN];

// ---------------------------------------------------------------------------
// Kernel P: precompute (exp(xm), exp(-xm)). 8.6M exps instead of 210M.
// ---------------------------------------------------------------------------
__global__ __launch_bounds__(256) void k_pre(const float* __restrict__ x,
                                             const int* __restrict__ mask) {
    size_t idx = (size_t)blockIdx.x * 256 + threadIdx.x;
    if (idx >= (size_t)BB * KCH * NN) return;
    int pix = (int)(idx & (NN - 1));
    int b   = (int)(idx / ((size_t)KCH * NN));
    float v = x[idx];
    int   m = mask[b * NN + pix];
    float xm = m ? v : 0.0f;
    float t = __expf(xm);
    float u = __expf(-xm);
    g_TU[idx] = make_float2(t, u);   // lo = t = e^{xm}, hi = u = e^{-xm}
}

// ---------------------------------------------------------------------------
// Kernel W: per-pixel window weights A[w].
//   e_w = max(u_c*t_b, t_c*u_b) = exp(|xm_c - xm_b|)   (0 for OOB since TU=0)
//   A[w] = sum_k conv[k] * e_w / sum_w e_w              (selected pixels only)
// Tile 16x16 pixels, halo 3 -> 22x22 (T,U) tile per channel, cp.async
// double-buffered over the k loop. Selected pixels compacted so fma-pipe
// warp-instructions scale with #selected, not #pixels.
// ---------------------------------------------------------------------------
__global__ __launch_bounds__(256, 1) void k_weights(const int* __restrict__ mask,
                                                    const float* __restrict__ conv) {
    constexpr int TS = 16, TW = 22, ST = 23;   // tile, halo width, padded stride
    __shared__ unsigned long long tu[2][TW * ST];
    __shared__ unsigned short lst[256];
    __shared__ int cnt_s;

    const int tid = threadIdx.x;
    const int b   = blockIdx.z;
    const int ti0 = blockIdx.y * TS, tj0 = blockIdx.x * TS;
    const int li  = tid >> 4, lj = tid & 15;
    const int gi  = ti0 + li, gj = tj0 + lj;

    if (tid == 0) cnt_s = 0;
    __syncthreads();
    const int msk = mask[b * NN + gi * NSIDE + gj];
    if (msk) {
        int pos = atomicAdd(&cnt_s, 1);
        lst[pos] = (unsigned short)tid;
    } else {
        // unselected pixels: A row is exactly zero
        const int pix = gi * NSIDE + gj;
#pragma unroll
        for (int w = 0; w < NW; w++)
            g_A[((size_t)w * BB + b) * NN + pix] = 0.0f;
    }
    __syncthreads();
    const int cnt = cnt_s;
    const bool active = tid < cnt;
    int li2 = 0, lj2 = 0;
    if (active) { int t2 = lst[tid]; li2 = t2 >> 4; lj2 = t2 & 15; }
    const int sbase = li2 * ST + lj2;

    // --- async tile loader: 22x22 float2, zero-fill out of bounds ---
    auto load_tile = [&](int k, int buf) {
        const float2* gsrc = g_TU + (size_t)(b * KCH + k) * NN;
        unsigned sdst = (unsigned)__cvta_generic_to_shared(&tu[buf][0]);
#pragma unroll
        for (int e0 = 0; e0 < 2; e0++) {
            int e = tid + e0 * 256;
            if (e < TW * TW) {
                int r = e / TW, c = e - r * TW;
                int gi2 = ti0 - 3 + r, gj2 = tj0 - 3 + c;
                bool ok = ((unsigned)gi2 < NSIDE) && ((unsigned)gj2 < NSIDE);
                int gic = min(max(gi2, 0), NSIDE - 1);
                int gjc = min(max(gj2, 0), NSIDE - 1);
                const void* src = (const void*)(gsrc + gic * NSIDE + gjc);
                unsigned dst = sdst + (unsigned)((r * ST + c) * 8);
                int sz = ok ? 8 : 0;   // src-size 0 -> zero fill (kills OOB taps)
                asm volatile("cp.async.ca.shared.global [%0], [%1], 8, %2;\n"
                             :: "r"(dst), "l"(src), "r"(sz));
            }
        }
        asm volatile("cp.async.commit_group;\n");
    };

    float acc[NW];
#pragma unroll
    for (int w = 0; w < NW; w++) acc[w] = 0.0f;

    load_tile(0, 0);
    for (int k = 0; k < KCH; k++) {
        if (k + 1 < KCH) {
            load_tile(k + 1, (k + 1) & 1);
            asm volatile("cp.async.wait_group 1;\n");
        } else {
            asm volatile("cp.async.wait_group 0;\n");
        }
        __syncthreads();
        if (active) {
            const unsigned long long* T = tu[k & 1];
            unsigned long long c64 = T[sbase + 3 * ST + 3];   // (t_c, u_c)
            unsigned clo, chi;
            asm("mov.b64 {%0,%1}, %2;" : "=r"(clo), "=r"(chi) : "l"(c64));
            unsigned long long Cw;                            // (u_c, t_c)
            asm("mov.b64 %0, {%1,%2};" : "=l"(Cw) : "r"(chi), "r"(clo));

            float e[NW];
            float s0 = 0.f, s1 = 0.f, s2 = 0.f, s3 = 0.f;
#pragma unroll
            for (int dy = 0; dy < 7; dy++) {
#pragma unroll
                for (int dx = 0; dx < 7; dx++) {
                    unsigned long long p = T[sbase + dy * ST + dx];  // (t_b,u_b)
                    unsigned long long mr;
                    asm("mul.rn.f32x2 %0, %1, %2;" : "=l"(mr) : "l"(Cw), "l"(p));
                    unsigned ra, rb;
                    asm("mov.b64 {%0,%1}, %2;" : "=r"(ra), "=r"(rb) : "l"(mr));
                    float ev = fmaxf(__uint_as_float(ra), __uint_as_float(rb));
                    const int w = dy * 7 + dx;
                    e[w] = ev;
                    if      ((w & 3) == 0) s0 += ev;
                    else if ((w & 3) == 1) s1 += ev;
                    else if ((w & 3) == 2) s2 += ev;
                    else                   s3 += ev;
                }
            }
            float S = (s0 + s1) + (s2 + s3);        // >= ~1 (center tap)
            float coeff = __fdividef(__ldg(conv + k), S);
#pragma unroll
            for (int w = 0; w < NW; w++) acc[w] = fmaf(coeff, e[w], acc[w]);
        }
        __syncthreads();
    }

    if (active) {
        const int pix = (ti0 + li2) * NSIDE + (tj0 + lj2);
#pragma unroll
        for (int w = 0; w < NW; w++)
            g_A[((size_t)w * BB + b) * NN + pix] = acc[w];
    }
}

// ---------------------------------------------------------------------------
// Kernel G: output gather.
//   y[b, q=(i,j), c] = sum_{du,dv in [-3,3]} A[w=(3-du)*7+(3-dv)][p=(i+du,j+dv)]
//                      * x2[b, c, p]
// ---------------------------------------------------------------------------
__global__ __launch_bounds__(256) void k_gather(const float* __restrict__ x2,
                                                float* __restrict__ out) {
    const int b  = blockIdx.z;
    const int tid = threadIdx.x;
    const int i2 = blockIdx.y * 16 + (tid >> 4);
    const int j2 = blockIdx.x * 16 + (tid & 15);

    float acc[CCH];
#pragma unroll
    for (int c = 0; c < CCH; c++) acc[c] = 0.0f;

    const float* x2b = x2 + (size_t)b * CCH * NN;

#pragma unroll 1
    for (int du = -3; du <= 3; du++) {
        const int pi = i2 + du;
        if ((unsigned)pi >= NSIDE) continue;
#pragma unroll 1
        for (int dv = -3; dv <= 3; dv++) {
            const int pj = j2 + dv;
            if ((unsigned)pj >= NSIDE) continue;
            const int w = (3 - du) * 7 + (3 - dv);
            const int p = pi * NSIDE + pj;
            const float a = g_A[((size_t)w * BB + b) * NN + p];
            const float* f = x2b + p;
#pragma unroll
            for (int c = 0; c < CCH; c++)
                acc[c] = fmaf(a, f[(size_t)c * NN], acc[c]);
        }
    }

    float* o = out + ((size_t)b * NN + i2 * NSIDE + j2) * CCH;
#pragma unroll
    for (int c = 0; c < CCH; c++) o[c] = acc[c];
}

// ---------------------------------------------------------------------------
// Launch
// ---------------------------------------------------------------------------
extern "C" void kernel_launch(void* const* d_in, const int* in_sizes, int n_in,
                              void* d_out, int out_size) {
    (void)in_sizes; (void)n_in; (void)out_size;
    const float* integ = (const float*)d_in[0];   // [B,K,N,N] f32
    const float* x2    = (const float*)d_in[1];   // [B,C,N*N] f32
    const int*   mask  = (const int*)d_in[2];     // [B,N,N]   i32
    const float* conv  = (const float*)d_in[3];   // [K]       f32
    float* out = (float*)d_out;                   // [B,N*N,C] f32

    const int total = BB * KCH * NN;
    k_pre<<<(total + 255) / 256, 256>>>(integ, mask);

    dim3 grid(NSIDE / 16, NSIDE / 16, BB);
    k_weights<<<grid, 256>>>(mask, conv);
    k_gather<<<grid, 256>>>(x2, out);
}

// round 9
// speedup vs baseline: 1.7241x; 1.7241x over previous
#include <cuda_runtime.h>
#include <cstdint>

// Problem constants (fixed by the dataset)
#define RWIN   3
#define NW     49          // (2R+1)^2
#define NSIDE  128
#define NN     (NSIDE*NSIDE)
#define KCH    131
#define CCH    21
#define BB     2

// Scratch (device globals; no allocation allowed)
// (t,u) = (exp(xm), exp(-xm)) pairs; stored as float4 for 16B-aligned vector IO.
__device__ float4 g_TU[(size_t)BB * KCH * NN / 2];
// g_A[w][b][pix] : per-window-tap mixing weights (49 planes, coalesced for gather)
__device__ float  g_A[(size_t)NW * BB * NN];

// ---------------------------------------------------------------------------
// Kernel P: precompute (exp(xm), exp(-xm)). float4-vectorized (4 px / thread).
// ---------------------------------------------------------------------------
__global__ __launch_bounds__(256) void k_pre(const float4* __restrict__ x,
                                             const int4* __restrict__ mask) {
    const int total4 = BB * KCH * NN / 4;
    int idx = blockIdx.x * 256 + threadIdx.x;
    if (idx >= total4) return;
    int pix4 = idx & (NN / 4 - 1);
    int b    = idx / (KCH * NN / 4);
    float4 v = x[idx];
    int4   m = mask[b * (NN / 4) + pix4];
    float x0 = m.x ? v.x : 0.0f;
    float x1 = m.y ? v.y : 0.0f;
    float x2 = m.z ? v.z : 0.0f;
    float x3 = m.w ? v.w : 0.0f;
    float4 o0, o1;
    o0.x = __expf(x0);  o0.y = __expf(-x0);
    o0.z = __expf(x1);  o0.w = __expf(-x1);
    o1.x = __expf(x2);  o1.y = __expf(-x2);
    o1.z = __expf(x3);  o1.w = __expf(-x3);
    g_TU[2 * (size_t)idx]     = o0;
    g_TU[2 * (size_t)idx + 1] = o1;
}

// ---------------------------------------------------------------------------
// Kernel W: per-pixel window weights A[w].
//   e_w = max(u_c*t_b, t_c*u_b) = exp(|xm_c - xm_b|)   (0 for OOB since TU=0)
//   A[w] = sum_k conv[k] * e_w / sum_w e_w              (selected pixels only)
//
// 8x8 pixel tile, 128 threads = 2 threads/pixel split by window ROW:
//   half0 -> dy in [0,3] (28 taps, includes center row), half1 -> dy in [4,6]
// Pair partial sums combined via shfl_xor(1) (pair lanes share the pixel, so
// the shfl participation mask is always pairwise-consistent).
// 3-deep cp.async pipeline over k with ONE __syncthreads per iteration.
// SMEM stride 26 words -> even/odd-lane LDS.64 word addrs disjoint mod 16
// (conflict-free).
// ---------------------------------------------------------------------------
#define TI  8
#define TJ  8
#define HWD 14      // halo tile = (TI+6) x (TJ+6)
#define STW 26      // smem row stride in 8-byte words  (STW % 4 == 2)

__global__ __launch_bounds__(128, 4) void k_weights(const int* __restrict__ mask,
                                                    const float* __restrict__ conv) {
    __shared__ unsigned long long tu[3][HWD * STW];   // 3 x 2912 B

    const int tid  = threadIdx.x;
    const int b    = blockIdx.z;
    const int ti0  = blockIdx.y * TI, tj0 = blockIdx.x * TJ;
    const int px   = tid >> 1, half = tid & 1;
    const int pi   = px >> 3, pj = px & 7;
    const int gi   = ti0 + pi, gj = tj0 + pj;
    const int pix  = gi * NSIDE + gj;
    const int msk  = mask[b * NN + pix];
    // smem base for this thread's tap rows: dy0 = 4*half
    const int base = (pi + 4 * half) * STW + pj;
    const int cbase = (pi + 3) * STW + (pj + 3);     // center (dy=3,dx=3)

    // --- async 14x14 float2 tile loader, zero-fill out of bounds ---
    auto load_tile = [&](int k, int buf) {
        const float2* gsrc = (const float2*)g_TU + (size_t)(b * KCH + k) * NN;
        unsigned sdst = (unsigned)__cvta_generic_to_shared(&tu[buf][0]);
#pragma unroll
        for (int e0 = 0; e0 < 2; e0++) {
            int e = tid + e0 * 128;
            if (e < HWD * HWD) {
                int r = e / HWD, c = e - r * HWD;
                int gi2 = ti0 - 3 + r, gj2 = tj0 - 3 + c;
                bool ok = ((unsigned)gi2 < NSIDE) && ((unsigned)gj2 < NSIDE);
                int gic = min(max(gi2, 0), NSIDE - 1);
                int gjc = min(max(gj2, 0), NSIDE - 1);
                const void* src = (const void*)(gsrc + gic * NSIDE + gjc);
                unsigned dst = sdst + (unsigned)((r * STW + c) * 8);
                int sz = ok ? 8 : 0;   // src-size 0 -> zero fill (kills OOB taps)
                asm volatile("cp.async.ca.shared.global [%0], [%1], 8, %2;\n"
                             :: "r"(dst), "l"(src), "r"(sz));
            }
        }
        asm volatile("cp.async.commit_group;\n");
    };

    float acc[28];
#pragma unroll
    for (int t = 0; t < 28; t++) acc[t] = 0.0f;

    load_tile(0, 0);
    load_tile(1, 1);

    for (int k = 0; k < KCH; k++) {
        asm volatile("cp.async.wait_group 1;\n");   // my group k complete
        __syncthreads();                            // buf k visible; buf (k+2)%3 free
        if (k + 2 < KCH) load_tile(k + 2, (k + 2) % 3);

        if (msk) {
            const unsigned long long* T = tu[k % 3];
            unsigned long long c64 = T[cbase];       // (t_c, u_c)
            unsigned clo, chi;
            asm("mov.b64 {%0,%1}, %2;" : "=r"(clo), "=r"(chi) : "l"(c64));
            unsigned long long Cw;                   // (u_c, t_c)
            asm("mov.b64 %0, {%1,%2};" : "=l"(Cw) : "r"(chi), "r"(clo));

            float e[28];
            float s = 0.0f;
#pragma unroll
            for (int r = 0; r < 4; r++) {
                if (r < 3 || half == 0) {            // half1 has only 3 rows
#pragma unroll
                    for (int dx = 0; dx < 7; dx++) {
                        unsigned long long p = T[base + r * STW + dx]; // (t_b,u_b)
                        unsigned long long mr;
                        asm("mul.rn.f32x2 %0, %1, %2;" : "=l"(mr) : "l"(Cw), "l"(p));
                        unsigned ra, rb;
                        asm("mov.b64 {%0,%1}, %2;" : "=r"(ra), "=r"(rb) : "l"(mr));
                        float ev = fmaxf(__uint_as_float(ra), __uint_as_float(rb));
                        e[r * 7 + dx] = ev;
                        s += ev;
                    }
                }
            }
            // pair lanes (2p, 2p+1) share the pixel -> same msk -> both here
            float stot = s + __shfl_xor_sync(__activemask(), s, 1);
            float coeff = __fdividef(__ldg(conv + k), stot);
#pragma unroll
            for (int t = 0; t < 28; t++)
                if (t < 28 - 7 * half)
                    acc[t] = fmaf(coeff, e[t], acc[t]);
        }
    }

    // write-out: half0 -> w 0..27, half1 -> w 28..48; unselected rows = 0 (acc==0)
    const int wb = half ? 28 : 0;
#pragma unroll
    for (int t = 0; t < 28; t++)
        if (t < 28 - 7 * half)
            g_A[((size_t)(wb + t) * BB + b) * NN + pix] = acc[t];
}

// ---------------------------------------------------------------------------
// Kernel G: output gather.
//   y[b, q=(i,j), c] = sum_{du,dv in [-3,3]} A[w=(3-du)*7+(3-dv)][p=(i+du,j+dv)]
//                      * x2[b, c, p]
// ---------------------------------------------------------------------------
__global__ __launch_bounds__(256) void k_gather(const float* __restrict__ x2,
                                                float* __restrict__ out) {
    const int b  = blockIdx.z;
    const int tid = threadIdx.x;
    const int i2 = blockIdx.y * 16 + (tid >> 4);
    const int j2 = blockIdx.x * 16 + (tid & 15);

    float acc[CCH];
#pragma unroll
    for (int c = 0; c < CCH; c++) acc[c] = 0.0f;

    const float* x2b = x2 + (size_t)b * CCH * NN;

#pragma unroll 1
    for (int du = -3; du <= 3; du++) {
        const int pi = i2 + du;
        if ((unsigned)pi >= NSIDE) continue;
#pragma unroll 1
        for (int dv = -3; dv <= 3; dv++) {
            const int pj = j2 + dv;
            if ((unsigned)pj >= NSIDE) continue;
            const int w = (3 - du) * 7 + (3 - dv);
            const int p = pi * NSIDE + pj;
            const float a = g_A[((size_t)w * BB + b) * NN + p];
            const float* f = x2b + p;
#pragma unroll
            for (int c = 0; c < CCH; c++)
                acc[c] = fmaf(a, f[(size_t)c * NN], acc[c]);
        }
    }

    float* o = out + ((size_t)b * NN + i2 * NSIDE + j2) * CCH;
#pragma unroll
    for (int c = 0; c < CCH; c++) o[c] = acc[c];
}

// ---------------------------------------------------------------------------
// Launch
// ---------------------------------------------------------------------------
extern "C" void kernel_launch(void* const* d_in, const int* in_sizes, int n_in,
                              void* d_out, int out_size) {
    (void)in_sizes; (void)n_in; (void)out_size;
    const float* integ = (const float*)d_in[0];   // [B,K,N,N] f32
    const float* x2    = (const float*)d_in[1];   // [B,C,N*N] f32
    const int*   mask  = (const int*)d_in[2];     // [B,N,N]   i32
    const float* conv  = (const float*)d_in[3];   // [K]       f32
    float* out = (float*)d_out;                   // [B,N*N,C] f32

    const int total4 = BB * KCH * NN / 4;
    k_pre<<<(total4 + 255) / 256, 256>>>((const float4*)integ, (const int4*)mask);

    dim3 gw(NSIDE / TJ, NSIDE / TI, BB);          // 16 x 16 x 2 = 512 blocks
    k_weights<<<gw, 128>>>(mask, conv);

    dim3 gg(NSIDE / 16, NSIDE / 16, BB);
    k_gather<<<gg, 256>>>(x2, out);
}